// round 2
// baseline (speedup 1.0000x reference)
#include <cuda_runtime.h>

#define BATCH 128
#define TLEN  1024
#define DIM   256
#define NBUF  64

// Scratch (static device arrays; no allocation allowed in kernel_launch)
__device__ float g_Q[(size_t)BATCH * TLEN * DIM];
__device__ float g_C[(size_t)BATCH * TLEN * DIM];
__device__ float g_R[(size_t)BATCH * TLEN * DIM];
__device__ float g_dummy[(size_t)BATCH * NBUF * DIM + BATCH];

// ----------------------------------------------------------------------------
// GEMM: Y[M,256] = X[M,256] @ W[256,256] + bias   (fp32, tiled 64x64x16)
// ----------------------------------------------------------------------------
__global__ void __launch_bounds__(256) gemm_bias_kernel(
    const float* __restrict__ X, const float* __restrict__ W,
    const float* __restrict__ bias, float* __restrict__ Y)
{
    __shared__ float As[16][64];   // [k][m]
    __shared__ float Bs[16][64];   // [k][n]

    const int tid = threadIdx.x;
    const int ty  = tid >> 4;      // 0..15
    const int tx  = tid & 15;      // 0..15
    const int m0  = blockIdx.x * 64;
    const int n0  = blockIdx.y * 64;
    const int lr  = tid >> 2;          // A-tile row 0..63
    const int lk  = (tid & 3) << 2;    // A-tile k offset 0,4,8,12

    float acc[4][4];
#pragma unroll
    for (int i = 0; i < 4; i++)
#pragma unroll
        for (int j = 0; j < 4; j++) acc[i][j] = 0.0f;

    for (int k0 = 0; k0 < DIM; k0 += 16) {
        float4 a4 = *(const float4*)(X + (size_t)(m0 + lr) * DIM + k0 + lk);
        As[lk + 0][lr] = a4.x;
        As[lk + 1][lr] = a4.y;
        As[lk + 2][lr] = a4.z;
        As[lk + 3][lr] = a4.w;
        float4 b4 = *(const float4*)(W + (size_t)(k0 + ty) * DIM + n0 + (tx << 2));
        *(float4*)(&Bs[ty][tx << 2]) = b4;
        __syncthreads();

#pragma unroll
        for (int k = 0; k < 16; k++) {
            float4 av = *(const float4*)(&As[k][ty << 2]);
            float4 bv = *(const float4*)(&Bs[k][tx << 2]);
            float ar[4] = {av.x, av.y, av.z, av.w};
            float br[4] = {bv.x, bv.y, bv.z, bv.w};
#pragma unroll
            for (int i = 0; i < 4; i++)
#pragma unroll
                for (int j = 0; j < 4; j++)
                    acc[i][j] = fmaf(ar[i], br[j], acc[i][j]);
        }
        __syncthreads();
    }

    float4 bb = *(const float4*)(bias + n0 + (tx << 2));
    float bbr[4] = {bb.x, bb.y, bb.z, bb.w};
#pragma unroll
    for (int i = 0; i < 4; i++) {
        float4 o;
        o.x = acc[i][0] + bbr[0];
        o.y = acc[i][1] + bbr[1];
        o.z = acc[i][2] + bbr[2];
        o.w = acc[i][3] + bbr[3];
        *(float4*)(Y + (size_t)(m0 + (ty << 2) + i) * DIM + n0 + (tx << 2)) = o;
    }
}

// ----------------------------------------------------------------------------
// Sequential scan: one CTA per batch, 256 threads (8 warps).
// Buffer (64x256) register-resident: warp w owns rows 8w..8w+7,
// lane l owns columns {l, l+32, ..., l+224}.
// ----------------------------------------------------------------------------
__global__ void __launch_bounds__(256, 1) scan_kernel(
    const float* __restrict__ Q, const float* __restrict__ C,
    const float* __restrict__ masks, const float* __restrict__ buf0,
    float* __restrict__ Rout, float* __restrict__ bufF, float* __restrict__ ptrF)
{
    const int b   = blockIdx.x;
    const int tid = threadIdx.x;
    const int w   = tid >> 5;
    const int l   = tid & 31;

    __shared__ float logits_sh[64];
    __shared__ float red_sh[8 * 256];

    float buf[8][8];
#pragma unroll
    for (int r = 0; r < 8; r++)
#pragma unroll
        for (int c = 0; c < 8; c++)
            buf[r][c] = buf0[(size_t)b * NBUF * DIM + (w * 8 + r) * DIM + l + 32 * c];

    int ptr = 0;
    const float scale = 0.0625f;  // 1/sqrt(256)
    const float* Qb = Q + (size_t)b * TLEN * DIM;
    const float* Cb = C + (size_t)b * TLEN * DIM;
    float*       Rb = Rout + (size_t)b * TLEN * DIM;
    const float* Mb = masks + (size_t)b * TLEN;

    for (int t = 0; t < TLEN; t++) {
        // episode reset
        float m = Mb[t];
        if (m != 1.0f) {
#pragma unroll
            for (int r = 0; r < 8; r++)
#pragma unroll
                for (int c = 0; c < 8; c++) buf[r][c] *= m;
            ptr = ptr * (int)m;
        }

        // load query slice
        float qv[8];
#pragma unroll
        for (int c = 0; c < 8; c++) qv[c] = Qb[(size_t)t * DIM + l + 32 * c];

        // logits: logit[n] = q . buf[n]  (warp-local rows, butterfly reduce)
#pragma unroll
        for (int r = 0; r < 8; r++) {
            float p = 0.0f;
#pragma unroll
            for (int c = 0; c < 8; c++) p = fmaf(qv[c], buf[r][c], p);
#pragma unroll
            for (int off = 16; off > 0; off >>= 1)
                p += __shfl_xor_sync(0xffffffffu, p, off);
            if (l == 0) logits_sh[w * 8 + r] = p * scale;
        }
        __syncthreads();

        // softmax over 64 logits, redundantly in every warp (no extra barrier)
        float l0 = logits_sh[l];
        float l1 = logits_sh[l + 32];
        float mx = fmaxf(l0, l1);
#pragma unroll
        for (int off = 16; off > 0; off >>= 1)
            mx = fmaxf(mx, __shfl_xor_sync(0xffffffffu, mx, off));
        float e0 = __expf(l0 - mx);
        float e1 = __expf(l1 - mx);
        float s  = e0 + e1;
#pragma unroll
        for (int off = 16; off > 0; off >>= 1)
            s += __shfl_xor_sync(0xffffffffu, s, off);
        float inv = 1.0f / s;

        float av[8];
#pragma unroll
        for (int r = 0; r < 8; r++) {
            int idx = w * 8 + r;                      // uniform per warp
            float src = (idx < 32) ? e0 : e1;
            av[r] = __shfl_sync(0xffffffffu, src, idx & 31) * inv;
        }

        // read_pre partials -> shared staging
#pragma unroll
        for (int c = 0; c < 8; c++) {
            float acc = 0.0f;
#pragma unroll
            for (int r = 0; r < 8; r++) acc = fmaf(av[r], buf[r][c], acc);
            red_sh[w * 256 + l + 32 * c] = acc;
        }
        __syncthreads();

        // cross-warp reduce + store read_pre
        {
            float s2 = 0.0f;
#pragma unroll
            for (int ww = 0; ww < 8; ww++) s2 += red_sh[ww * 256 + tid];
            Rb[(size_t)t * DIM + tid] = s2;
        }

        // scatter-write compressed vector at slot ptr (after the read)
        if ((ptr >> 3) == w) {
            float cv[8];
#pragma unroll
            for (int c = 0; c < 8; c++) cv[c] = Cb[(size_t)t * DIM + l + 32 * c];
            int r = ptr & 7;
#pragma unroll
            for (int rr = 0; rr < 8; rr++)
                if (rr == r) {
#pragma unroll
                    for (int c = 0; c < 8; c++) buf[rr][c] = cv[c];
                }
        }
        ptr = (ptr + 1) & (NBUF - 1);
    }

    // final buffer + pointer
#pragma unroll
    for (int r = 0; r < 8; r++)
#pragma unroll
        for (int c = 0; c < 8; c++)
            bufF[(size_t)b * NBUF * DIM + (w * 8 + r) * DIM + l + 32 * c] = buf[r][c];
    if (tid == 0) ptrF[b] = (float)ptr;
}

// ----------------------------------------------------------------------------
extern "C" void kernel_launch(void* const* d_in, const int* in_sizes, int n_in,
                              void* d_out, int out_size)
{
    const float* hidden  = (const float*)d_in[0];
    const float* masks   = (const float*)d_in[1];
    const float* buffer0 = (const float*)d_in[2];
    const float* Wq      = (const float*)d_in[3];
    const float* bq      = (const float*)d_in[4];
    const float* Wo      = (const float*)d_in[5];
    const float* bo      = (const float*)d_in[6];
    const float* Wc      = (const float*)d_in[7];
    const float* bc      = (const float*)d_in[8];

    float* Qp; float* Cp; float* Rp; float* Dp;
    cudaGetSymbolAddress((void**)&Qp, g_Q);
    cudaGetSymbolAddress((void**)&Cp, g_C);
    cudaGetSymbolAddress((void**)&Rp, g_R);
    cudaGetSymbolAddress((void**)&Dp, g_dummy);

    float* out      = (float*)d_out;
    float* read_seq = out;
    const size_t n_read = (size_t)BATCH * TLEN * DIM;
    const size_t n_buf  = (size_t)BATCH * NBUF * DIM;

    float* bufF;
    float* ptrF;
    if ((size_t)out_size >= n_read + n_buf + BATCH) {
        bufF = out + n_read;
        ptrF = bufF + n_buf;
    } else {   // fallback: only read_seq compared
        bufF = Dp;
        ptrF = Dp + n_buf;
    }

    const int M = BATCH * TLEN;           // 131072
    dim3 ggrid(M / 64, DIM / 64);

    gemm_bias_kernel<<<ggrid, 256>>>(hidden, Wq, bq, Qp);
    gemm_bias_kernel<<<ggrid, 256>>>(hidden, Wc, bc, Cp);
    scan_kernel<<<BATCH, 256>>>(Qp, Cp, masks, buffer0, Rp, bufF, ptrF);
    gemm_bias_kernel<<<ggrid, 256>>>(Rp, Wo, bo, read_seq);
}